// round 8
// baseline (speedup 1.0000x reference)
#include <cuda_runtime.h>

// x shape (N=2, D=192, H=256, W=512), float32.
#define DIMD 192
#define HWD  131072          // H*W
#define BLK  128
#define NPIX 262144          // N*H*W
#define SMEM_BYTES (DIMD * BLK * 4)   // 96 KB -> 2 CTAs/SM

// Correctly-rounded a/5 via Markstein final step with exact seed y=RN(1/5).
// Bit-identical to __fdiv_rn(a,5) for all normal a (proven IEEE sequence),
// 3 FMA-pipe ops instead of MUFU.RCP + fixup chain. Inputs here are in [0,5].
__device__ __forceinline__ float qdiv5(float a)
{
    const float y  = 0.2f;              // RN(1/5)
    float q0 = a * y;                   // RN(a*y)
    float r  = fmaf(-5.0f, q0, a);      // exact residual (fma)
    return fmaf(r, y, q0);              // RN(a/5)
}

// Blur at depth d from raw x in smem (exact reference add order, zero-padded),
// with optional interval [ZA,ZB] zeroed AFTER the blur (x_blur * ~mask).
template<bool HASZ>
__device__ __forceinline__ float blur_at(const float* __restrict__ sp, int d,
                                         int ZA, int ZB)
{
    if (HASZ && (d >= ZA && d <= ZB)) return 0.0f;
    float a = (d >= 2)        ? sp[(d - 2) * BLK] : 0.0f;
    a = a + ((d >= 1)         ? sp[(d - 1) * BLK] : 0.0f);
    a = a +                     sp[d * BLK];
    a = a + ((d + 1 < DIMD)   ? sp[(d + 1) * BLK] : 0.0f);
    a = a + ((d + 2 < DIMD)   ? sp[(d + 2) * BLK] : 0.0f);
    return qdiv5(a);
}

// Right/left slope scans from argmax -> modal interval [lo,hi].
template<bool HASZ>
__device__ __forceinline__ void scans(const float* __restrict__ sp, int idx, float bq,
                                      int ZA, int ZB, int& lo, int& hi)
{
    int i = idx + 1;
    float bprev = bq;
    while (i < DIMD) {
        float bi = blur_at<HASZ>(sp, i, ZA, ZB);
        if (bi > bprev) break;                  // first diff > 0 after idx
        bprev = bi; ++i;
    }
    const int ir = i - 1;                       // i==D: sentinel fires -> D-1

    i = idx;
    float bcur = bq;
    while (i >= 1) {
        float bm = blur_at<HASZ>(sp, i - 1, ZA, ZB);
        if (bcur < bm) break;                   // last diff < 0 at/below idx
        bcur = bm; --i;
    }
    const int il = i;                           // i==0: sentinel fires

    int dev = 2 * idx - ir - il; if (dev < 0) dev = -dev;
    if (dev < 3) { lo = il; hi = ir; }
    else {
        int rr = min(ir - idx, idx - il);
        lo = idx - rr; hi = idx + rr;
    }
}

// Continue argmax of blur(raw x) over d in [a, bEnd). (Blur always uses raw x:
// the reference zeroes AFTER blurring, and zeros can never win vs positives.)
__device__ __forceinline__ void seg_argmax(const float* __restrict__ sp, int a, int bEnd,
                                           float& bestQ, int& idx)
{
    float xm2 = (a - 2 >= 0)   ? sp[(a - 2) * BLK] : 0.0f;
    float xm1 = (a - 1 >= 0)   ? sp[(a - 1) * BLK] : 0.0f;
    float x0  =                  sp[a * BLK];
    float x1  = (a + 1 < DIMD) ? sp[(a + 1) * BLK] : 0.0f;
    #pragma unroll 4
    for (int d = a; d < bEnd; ++d) {
        float x2  = (d + 2 < DIMD) ? sp[(d + 2) * BLK] : 0.0f;
        float q   = qdiv5((((xm2 + xm1) + x0) + x1) + x2);
        bool  u   = (q > bestQ);                // strict -> first occurrence
        bestQ = u ? q : bestQ;
        idx   = u ? d : idx;
        xm2 = xm1; xm1 = x0; x0 = x1; x1 = x2;
    }
}

__global__ void __launch_bounds__(BLK, 2)
dme_kernel(const float* __restrict__ x, float* __restrict__ out)
{
    extern __shared__ float s[];                // [DIMD][BLK]
    const int tid  = threadIdx.x;
    const int pix0 = blockIdx.x * BLK;          // blocks never straddle n
    const int n    = pix0 >> 17;                // / HWD
    const int hw0  = pix0 & (HWD - 1);
    const float* __restrict__ gb = x + (size_t)n * DIMD * HWD + hw0;

    // ---- cooperative vectorized stage-in: 6144 float4s per block,
    //      48 LDG.128 + STS.128 per thread, fully independent (high MLP) ----
    #pragma unroll 8
    for (int i = 0; i < (DIMD * BLK / 4) / BLK; ++i) {   // 48 iters
        int flat = i * BLK + tid;               // float4 index, 32 per d-row
        int d    = flat >> 5;
        int p4   = flat & 31;
        float4 v = *(const float4*)(gb + (size_t)d * HWD + p4 * 4);
        *(float4*)(&s[d * BLK + p4 * 4]) = v;
    }
    __syncthreads();

    const float* __restrict__ sp = s + tid;     // lane-private bank column

    // ---- pass-1 argmax over blur (rolling window, 1 LDS/iter) ----
    float bestQ = -1.0f; int idx = 0;
    {
        float xm2 = 0.0f, xm1 = 0.0f, x0 = sp[0], x1 = sp[BLK];
        #pragma unroll 4
        for (int d = 0; d < DIMD; ++d) {
            float x2 = (d + 2 < DIMD) ? sp[(d + 2) * BLK] : 0.0f;
            float q  = qdiv5((((xm2 + xm1) + x0) + x1) + x2);
            bool  u  = (q > bestQ);
            bestQ = u ? q : bestQ;
            idx   = u ? d : idx;
            xm2 = xm1; xm1 = x0; x0 = x1; x1 = x2;
        }
    }

    int lo1, hi1;
    scans<false>(sp, idx, bestQ, 0, -1, lo1, hi1);

    // ---- pass-2 argmax over the complement of [lo1,hi1] only ----
    float bq2 = -1.0f; int idx2 = 0;
    if (lo1 > 0)        seg_argmax(sp, 0, lo1, bq2, idx2);
    if (hi1 < DIMD - 1) seg_argmax(sp, hi1 + 1, DIMD, bq2, idx2);
    int lo2, hi2;
    scans<true>(sp, idx2, bq2, lo1, hi1, lo2, hi2);

    // ---- narrow final reductions: y on [lo1,hi1], z on [lo2,hi2] \ [lo1,hi1] ----
    float sy = 0.0f, syd = 0.0f, sz = 0.0f, szd = 0.0f;
    for (int d = lo1; d <= hi1; ++d) {
        float v = sp[d * BLK];
        sy += v; syd = fmaf(v, (float)d, syd);
    }
    for (int d = lo2; d <= hi2; ++d) {
        if (d >= lo1 && d <= hi1) continue;
        float v = sp[d * BLK];
        sz += v; szd = fmaf(v, (float)d, szd);
    }

    const bool  py  = (sy >= sz);
    const float num = py ? syd : szd;
    const float den = py ? sy  : sz;            // > 0 guaranteed (x > 0)
    out[pix0 + tid] = __fdiv_rn(num, den);
}

extern "C" void kernel_launch(void* const* d_in, const int* in_sizes, int n_in,
                              void* d_out, int out_size)
{
    const float* x   = (const float*)d_in[0];
    float*       out = (float*)d_out;

    cudaFuncSetAttribute(dme_kernel,
                         cudaFuncAttributeMaxDynamicSharedMemorySize, SMEM_BYTES);

    dme_kernel<<<NPIX / BLK, BLK, SMEM_BYTES>>>(x, out);
}

// round 9
// speedup vs baseline: 1.0011x; 1.0011x over previous
#include <cuda_runtime.h>

// x shape (N=2, D=192, H=256, W=512), float32.
#define DIMD 192
#define HWD  131072          // H*W
#define BLK  128
#define NPIX 262144          // N*H*W
#define SMEM_BYTES (DIMD * BLK * 4)   // 96 KB -> 2 CTAs/SM

// Correctly-rounded a/5 via Markstein final step with exact seed y=RN(1/5).
// Bit-identical to __fdiv_rn(a,5) for all normal a (proven IEEE sequence),
// 3 FMA-pipe ops instead of MUFU.RCP + fixup chain. Inputs here are in [0,5].
__device__ __forceinline__ float qdiv5(float a)
{
    const float y  = 0.2f;              // RN(1/5)
    float q0 = a * y;                   // RN(a*y)
    float r  = fmaf(-5.0f, q0, a);      // exact residual (fma)
    return fmaf(r, y, q0);              // RN(a/5)
}

// Blur at depth d from raw x in smem (exact reference add order, zero-padded),
// with optional interval [ZA,ZB] zeroed AFTER the blur (x_blur * ~mask).
template<bool HASZ>
__device__ __forceinline__ float blur_at(const float* __restrict__ sp, int d,
                                         int ZA, int ZB)
{
    if (HASZ && (d >= ZA && d <= ZB)) return 0.0f;
    float a = (d >= 2)        ? sp[(d - 2) * BLK] : 0.0f;
    a = a + ((d >= 1)         ? sp[(d - 1) * BLK] : 0.0f);
    a = a +                     sp[d * BLK];
    a = a + ((d + 1 < DIMD)   ? sp[(d + 1) * BLK] : 0.0f);
    a = a + ((d + 2 < DIMD)   ? sp[(d + 2) * BLK] : 0.0f);
    return qdiv5(a);
}

// Right/left slope scans from argmax -> modal interval [lo,hi].
template<bool HASZ>
__device__ __forceinline__ void scans(const float* __restrict__ sp, int idx, float bq,
                                      int ZA, int ZB, int& lo, int& hi)
{
    int i = idx + 1;
    float bprev = bq;
    while (i < DIMD) {
        float bi = blur_at<HASZ>(sp, i, ZA, ZB);
        if (bi > bprev) break;                  // first diff > 0 after idx
        bprev = bi; ++i;
    }
    const int ir = i - 1;                       // i==D: sentinel fires -> D-1

    i = idx;
    float bcur = bq;
    while (i >= 1) {
        float bm = blur_at<HASZ>(sp, i - 1, ZA, ZB);
        if (bcur < bm) break;                   // last diff < 0 at/below idx
        bcur = bm; --i;
    }
    const int il = i;                           // i==0: sentinel fires

    int dev = 2 * idx - ir - il; if (dev < 0) dev = -dev;
    if (dev < 3) { lo = il; hi = ir; }
    else {
        int rr = min(ir - idx, idx - il);
        lo = idx - rr; hi = idx + rr;
    }
}

// Continue argmax of blur(raw x) over d in [a, bEnd). (Blur always uses raw x:
// the reference zeroes AFTER blurring, and zeros can never win vs positives.)
__device__ __forceinline__ void seg_argmax(const float* __restrict__ sp, int a, int bEnd,
                                           float& bestQ, int& idx)
{
    float xm2 = (a - 2 >= 0)   ? sp[(a - 2) * BLK] : 0.0f;
    float xm1 = (a - 1 >= 0)   ? sp[(a - 1) * BLK] : 0.0f;
    float x0  =                  sp[a * BLK];
    float x1  = (a + 1 < DIMD) ? sp[(a + 1) * BLK] : 0.0f;
    #pragma unroll 4
    for (int d = a; d < bEnd; ++d) {
        float x2  = (d + 2 < DIMD) ? sp[(d + 2) * BLK] : 0.0f;
        float q   = qdiv5((((xm2 + xm1) + x0) + x1) + x2);
        bool  u   = (q > bestQ);                // strict -> first occurrence
        bestQ = u ? q : bestQ;
        idx   = u ? d : idx;
        xm2 = xm1; xm1 = x0; x0 = x1; x1 = x2;
    }
}

__global__ void __launch_bounds__(BLK, 2)
dme_kernel(const float* __restrict__ x, float* __restrict__ out)
{
    extern __shared__ float s[];                // [DIMD][BLK]
    const int tid  = threadIdx.x;
    const int pix0 = blockIdx.x * BLK;          // blocks never straddle n
    const int n    = pix0 >> 17;                // / HWD
    const int hw0  = pix0 & (HWD - 1);
    const float* __restrict__ gb = x + (size_t)n * DIMD * HWD + hw0;

    // ---- cooperative vectorized stage-in: 6144 float4s per block,
    //      48 LDG.128 + STS.128 per thread, fully independent (high MLP) ----
    #pragma unroll 8
    for (int i = 0; i < (DIMD * BLK / 4) / BLK; ++i) {   // 48 iters
        int flat = i * BLK + tid;               // float4 index, 32 per d-row
        int d    = flat >> 5;
        int p4   = flat & 31;
        float4 v = *(const float4*)(gb + (size_t)d * HWD + p4 * 4);
        *(float4*)(&s[d * BLK + p4 * 4]) = v;
    }
    __syncthreads();

    const float* __restrict__ sp = s + tid;     // lane-private bank column

    // ---- pass-1 argmax over blur (rolling window, 1 LDS/iter) ----
    float bestQ = -1.0f; int idx = 0;
    {
        float xm2 = 0.0f, xm1 = 0.0f, x0 = sp[0], x1 = sp[BLK];
        #pragma unroll 4
        for (int d = 0; d < DIMD; ++d) {
            float x2 = (d + 2 < DIMD) ? sp[(d + 2) * BLK] : 0.0f;
            float q  = qdiv5((((xm2 + xm1) + x0) + x1) + x2);
            bool  u  = (q > bestQ);
            bestQ = u ? q : bestQ;
            idx   = u ? d : idx;
            xm2 = xm1; xm1 = x0; x0 = x1; x1 = x2;
        }
    }

    int lo1, hi1;
    scans<false>(sp, idx, bestQ, 0, -1, lo1, hi1);

    // ---- pass-2 argmax over the complement of [lo1,hi1] only ----
    float bq2 = -1.0f; int idx2 = 0;
    if (lo1 > 0)        seg_argmax(sp, 0, lo1, bq2, idx2);
    if (hi1 < DIMD - 1) seg_argmax(sp, hi1 + 1, DIMD, bq2, idx2);
    int lo2, hi2;
    scans<true>(sp, idx2, bq2, lo1, hi1, lo2, hi2);

    // ---- narrow final reductions: y on [lo1,hi1], z on [lo2,hi2] \ [lo1,hi1] ----
    float sy = 0.0f, syd = 0.0f, sz = 0.0f, szd = 0.0f;
    for (int d = lo1; d <= hi1; ++d) {
        float v = sp[d * BLK];
        sy += v; syd = fmaf(v, (float)d, syd);
    }
    for (int d = lo2; d <= hi2; ++d) {
        if (d >= lo1 && d <= hi1) continue;
        float v = sp[d * BLK];
        sz += v; szd = fmaf(v, (float)d, szd);
    }

    const bool  py  = (sy >= sz);
    const float num = py ? syd : szd;
    const float den = py ? sy  : sz;            // > 0 guaranteed (x > 0)
    out[pix0 + tid] = __fdiv_rn(num, den);
}

extern "C" void kernel_launch(void* const* d_in, const int* in_sizes, int n_in,
                              void* d_out, int out_size)
{
    const float* x   = (const float*)d_in[0];
    float*       out = (float*)d_out;

    cudaFuncSetAttribute(dme_kernel,
                         cudaFuncAttributeMaxDynamicSharedMemorySize, SMEM_BYTES);

    dme_kernel<<<NPIX / BLK, BLK, SMEM_BYTES>>>(x, out);
}